// round 7
// baseline (speedup 1.0000x reference)
#include <cuda_runtime.h>
#include <cuda_bf16.h>
#include <math.h>

// Problem constants (from reference): B=8, N=256, MAX_DIM=2, D=4, EPS=1e-8
#define NP 256
#define NCELL 16   // B * MAX_DIM

__device__ float g_partial[NCELL];
__device__ unsigned int g_count;   // static-init 0; atomicInc wraps back to 0

// 16 blocks x 128 threads. Block = one (batch, dim) cell. Threads 0..63 sort
// the set1 projection, threads 64..127 sort set2, FOUR elements per thread
// (e = 4t..4t+3; each warp spans 128 contiguous elements). Stage dispatch:
//   j in {1,2}  : in-register compare-exchange            (15 stages)
//   j in {4..64}: shfl_xor within warp (lane mask j>>2)   (20 stages)
//   j == 128    : single smem exchange (k=256 -> asc all-true)
// Sorted matching == optimal assignment for 1D L1 cost; the 2B LAPs come in
// transpose pairs with equal totals -> factor 2. Last finishing block sums the
// 16 per-cell partials in fixed index order (deterministic) into out[0].
__global__ __launch_bounds__(128)
void hungarian_cells_kernel(const float* __restrict__ set1,
                            const float* __restrict__ set2,
                            float* __restrict__ out) {
    __shared__ float sbuf[512];     // [0:256) set1 half, [256:512) set2 half
    __shared__ float wsum[2];

    const int cell = blockIdx.x;    // 0..15
    const int b    = cell >> 1;
    const int dim  = cell & 1;
    const float fdim = (float)dim;

    const int tid  = threadIdx.x;   // 0..127
    const int half = tid >> 6;      // 0 = set1 array, 1 = set2 array
    const int t    = tid & 63;      // thread index within array
    const int lane = tid & 31;

    // --- projection: elements e = 4t .. 4t+3 ---
    float v[4];
    if (half == 0) {
        const float4* s1 = (const float4*)set1 + (size_t)b * NP + 4 * t;
        #pragma unroll
        for (int r = 0; r < 4; r++) {
            float4 p = s1[r];
            bool m = (p.z == fdim);
            v[r] = (m ? p.x : 0.0f) + sqrtf((m ? p.y : 0.0f) + 1e-8f) * 0.5f;
        }
    } else {
        const float4* s2 = (const float4*)set2 + (size_t)b * NP + 4 * t;
        #pragma unroll
        for (int r = 0; r < 4; r++) {
            float4 q = s2[r];
            // jnp.argmax over (c2, c3): first max wins -> label 1 iff c3 > c2
            bool m = (((q.w > q.z) ? 1 : 0) == dim);
            v[r] = (m ? q.x : 0.0f) + sqrtf((m ? q.y : 0.0f) + 1e-8f) * 0.5f;
        }
    }

    // --- bitonic sort of 256 elements, 4 per thread ---
    #pragma unroll
    for (int k = 2; k <= NP; k <<= 1) {
        #pragma unroll
        for (int j = k >> 1; j > 0; j >>= 1) {
            if (j >= 128) {
                // single cross-warp stage: k=256 so asc is true for all e
                ((float4*)(sbuf + half * 256 + 4 * t))[0] =
                    make_float4(v[0], v[1], v[2], v[3]);
                __syncthreads();
                float4 o = ((float4*)(sbuf + half * 256 + ((4 * t) ^ 128)))[0];
                const bool takeMax = (t & 32) != 0;
                v[0] = takeMax ? fmaxf(v[0], o.x) : fminf(v[0], o.x);
                v[1] = takeMax ? fmaxf(v[1], o.y) : fminf(v[1], o.y);
                v[2] = takeMax ? fmaxf(v[2], o.z) : fminf(v[2], o.z);
                v[3] = takeMax ? fmaxf(v[3], o.w) : fminf(v[3], o.w);
            } else if (j >= 4) {
                const int lm = j >> 2;                     // partner lane mask
                const bool asc = (((4 * t) & k) == 0);     // same for r=0..3
                const bool takeMax = (((lane & lm) != 0) == asc);
                #pragma unroll
                for (int r = 0; r < 4; r++) {
                    float o = __shfl_xor_sync(0xffffffffu, v[r], lm);
                    v[r] = takeMax ? fmaxf(v[r], o) : fminf(v[r], o);
                }
            } else {
                // in-register: pairs (r, r^j)
                #pragma unroll
                for (int r = 0; r < 4; r++) {
                    const int p = r ^ j;
                    if (p > r) {
                        const bool asc = (((4 * t + r) & k) == 0);
                        float lo = fminf(v[r], v[p]);
                        float hi = fmaxf(v[r], v[p]);
                        v[r] = asc ? lo : hi;
                        v[p] = asc ? hi : lo;
                    }
                }
            }
        }
    }

    // --- L1 diff of sorted sequences ---
    __syncthreads();                 // protect sbuf reuse vs j=128 reads
    if (half == 1)
        ((float4*)(sbuf + 256 + 4 * t))[0] = make_float4(v[0], v[1], v[2], v[3]);
    __syncthreads();
    float d = 0.0f;
    if (half == 0) {
        float4 o = ((float4*)(sbuf + 256 + 4 * t))[0];
        d = fabsf(v[0] - o.x) + fabsf(v[1] - o.y)
          + fabsf(v[2] - o.z) + fabsf(v[3] - o.w);
    }
    #pragma unroll
    for (int off = 16; off > 0; off >>= 1)
        d += __shfl_xor_sync(0xffffffffu, d, off);
    if (half == 0 && lane == 0) wsum[t >> 5] = d;   // warps 0,1
    __syncthreads();

    if (tid == 0) {
        float s = wsum[0] + wsum[1];
        // transpose-pair symmetry -> factor 2; each LAP averaged over N
        g_partial[cell] = s * (2.0f / (float)NP);
        __threadfence();
        unsigned int old = atomicInc(&g_count, NCELL - 1);   // 15 -> wraps 0
        if (old == NCELL - 1) {          // last block: all partials visible
            float tot = 0.0f;
            #pragma unroll
            for (int i = 0; i < NCELL; i++) tot += __ldcg(&g_partial[i]);
            out[0] = tot;
        }
    }
}

extern "C" void kernel_launch(void* const* d_in, const int* in_sizes, int n_in,
                              void* d_out, int out_size) {
    const float* set1 = (const float*)d_in[0];
    const float* set2 = (const float*)d_in[1];
    float* out = (float*)d_out;

    hungarian_cells_kernel<<<NCELL, 128>>>(set1, set2, out);
}

// round 9
// speedup vs baseline: 1.1822x; 1.1822x over previous
#include <cuda_runtime.h>
#include <cuda_bf16.h>
#include <math.h>

// Problem constants (from reference): B=8, N=256, MAX_DIM=2, D=4, EPS=1e-8
#define NP 256
#define NBLK 8     // one block per batch
#define NCELL 16   // B * MAX_DIM partial sums

__device__ float g_partial[NCELL];
__device__ unsigned int g_count;   // static-init 0; atomicInc wraps back to 0

// 8 blocks x 256 threads. Block = one batch; four 64-thread groups:
//   group 0: set1/dim0   group 1: set2/dim0
//   group 2: set1/dim1   group 3: set2/dim1
// Each group sorts its 256-element projection with 4 elements/thread
// (e = 4t..4t+3; each warp spans 128 contiguous elements):
//   j in {1,2}  : in-register compare-exchange            (15 stages)
//   j in {4..64}: shfl_xor within warp (lane mask j>>2)   (20 stages)
//   j == 128    : single smem exchange (k=256 -> asc all-true)
// 8 warps/block = 2 per SMSP, so the shfl chains of co-resident warps
// interleave and hide SHFL latency (the R7 failure mode).
// Sorted matching == optimal assignment for 1D L1 cost; the 2B LAPs come in
// transpose pairs with equal totals -> factor 2. Last finishing block sums the
// 16 per-cell partials in fixed index order (deterministic) into out[0].
__global__ __launch_bounds__(256)
void hungarian_batch_kernel(const float* __restrict__ set1,
                            const float* __restrict__ set2,
                            float* __restrict__ out) {
    __shared__ float sbuf[1024];    // 4 groups x 256 elements
    __shared__ float wsum[8];       // per-warp diff partials

    const int b = blockIdx.x;       // batch 0..7

    const int tid   = threadIdx.x;  // 0..255
    const int group = tid >> 6;     // 0..3
    const int t     = tid & 63;     // thread index within group
    const int lane  = tid & 31;
    const int dim   = group >> 1;   // 0,0,1,1
    const int isS2  = group & 1;    // 0 = set1, 1 = set2
    const float fdim = (float)dim;

    // --- projection: elements e = 4t .. 4t+3 ---
    float v[4];
    {
        const float4* src = (const float4*)(isS2 ? set2 : set1)
                          + (size_t)b * NP + 4 * t;
        #pragma unroll
        for (int r = 0; r < 4; r++) {
            float4 p = src[r];
            bool m;
            if (!isS2) {
                m = (p.z == fdim);
            } else {
                // jnp.argmax over (c2, c3): first max wins -> 1 iff c3 > c2
                m = (((p.w > p.z) ? 1 : 0) == dim);
            }
            v[r] = (m ? p.x : 0.0f) + sqrtf((m ? p.y : 0.0f) + 1e-8f) * 0.5f;
        }
    }

    // --- bitonic sort of 256 elements, 4 per thread ---
    #pragma unroll
    for (int k = 2; k <= NP; k <<= 1) {
        #pragma unroll
        for (int j = k >> 1; j > 0; j >>= 1) {
            if (j >= 128) {
                // single cross-warp stage: k=256 so asc is true for all e
                ((float4*)(sbuf + group * 256 + 4 * t))[0] =
                    make_float4(v[0], v[1], v[2], v[3]);
                __syncthreads();
                float4 o = ((float4*)(sbuf + group * 256 + ((4 * t) ^ 128)))[0];
                const bool takeMax = (t & 32) != 0;
                v[0] = takeMax ? fmaxf(v[0], o.x) : fminf(v[0], o.x);
                v[1] = takeMax ? fmaxf(v[1], o.y) : fminf(v[1], o.y);
                v[2] = takeMax ? fmaxf(v[2], o.z) : fminf(v[2], o.z);
                v[3] = takeMax ? fmaxf(v[3], o.w) : fminf(v[3], o.w);
            } else if (j >= 4) {
                const int lm = j >> 2;                     // partner lane mask
                const bool asc = (((4 * t) & k) == 0);     // same for r=0..3
                const bool takeMax = (((lane & lm) != 0) == asc);
                #pragma unroll
                for (int r = 0; r < 4; r++) {
                    float o = __shfl_xor_sync(0xffffffffu, v[r], lm);
                    v[r] = takeMax ? fmaxf(v[r], o) : fminf(v[r], o);
                }
            } else {
                // in-register: pairs (r, r^j)
                #pragma unroll
                for (int r = 0; r < 4; r++) {
                    const int p = r ^ j;
                    if (p > r) {
                        const bool asc = (((4 * t + r) & k) == 0);
                        float lo = fminf(v[r], v[p]);
                        float hi = fmaxf(v[r], v[p]);
                        v[r] = asc ? lo : hi;
                        v[p] = asc ? hi : lo;
                    }
                }
            }
        }
    }

    // --- L1 diff of sorted sequences (group 2g vs 2g+1) ---
    __syncthreads();                 // protect sbuf reuse vs j=128 reads
    if (isS2)
        ((float4*)(sbuf + group * 256 + 4 * t))[0] =
            make_float4(v[0], v[1], v[2], v[3]);
    __syncthreads();
    float d = 0.0f;
    if (!isS2) {
        float4 o = ((float4*)(sbuf + (group + 1) * 256 + 4 * t))[0];
        d = fabsf(v[0] - o.x) + fabsf(v[1] - o.y)
          + fabsf(v[2] - o.z) + fabsf(v[3] - o.w);
    }
    #pragma unroll
    for (int off = 16; off > 0; off >>= 1)
        d += __shfl_xor_sync(0xffffffffu, d, off);
    if (lane == 0) wsum[tid >> 5] = d;   // warps 0,1 (dim0) and 4,5 (dim1)
    __syncthreads();

    if (tid == 0) {
        // transpose-pair symmetry -> factor 2; each LAP averaged over N
        const float scale = 2.0f / (float)NP;
        g_partial[2 * b + 0] = (wsum[0] + wsum[1]) * scale;  // dim 0
        g_partial[2 * b + 1] = (wsum[4] + wsum[5]) * scale;  // dim 1
        __threadfence();
        unsigned int old = atomicInc(&g_count, NBLK - 1);    // 7 -> wraps 0
        if (old == NBLK - 1) {           // last block: all partials visible
            float tot = 0.0f;
            #pragma unroll
            for (int i = 0; i < NCELL; i++) tot += __ldcg(&g_partial[i]);
            out[0] = tot;
        }
    }
}

extern "C" void kernel_launch(void* const* d_in, const int* in_sizes, int n_in,
                              void* d_out, int out_size) {
    const float* set1 = (const float*)d_in[0];
    const float* set2 = (const float*)d_in[1];
    float* out = (float*)d_out;

    hungarian_batch_kernel<<<NBLK, 256>>>(set1, set2, out);
}